// round 13
// baseline (speedup 1.0000x reference)
#include <cuda_runtime.h>
#include <cuda_bf16.h>
#include <cstdint>
#include <math.h>

#define BB 32768
#define EE 16
#define MM 64
#define DD 256
#define RT 128
#define NT 256

#define O_W ((size_t)0)
#define O_S ((size_t)BB)
#define O_Y ((size_t)(2*BB))
#define O_G (O_Y + (size_t)BB*EE*DD)
#define O_A (O_G + (size_t)BB*EE)

// preconverted bf16 hi/lo operands
__device__ __nv_bfloat16 g_Khi[EE*MM*DD];
__device__ __nv_bfloat16 g_Klo[EE*MM*DD];
__device__ __nv_bfloat16 g_Vthi[EE*DD*MM];   // [E][D][M]
__device__ __nv_bfloat16 g_Vtlo[EE*DD*MM];
__device__ __nv_bfloat16 g_wghi[EE*DD];
__device__ __nv_bfloat16 g_wglo[EE*DD];

// smem map: K double-buffered, V single-rotate, g/xn staging
#define S_KA 0        // 65536: K bufA (hi @+0, lo @+32768)
#define S_KB 65536    // 65536: K bufB
#define S_V  131072   // 65536: V (hi @+0, lo @+32768); wg in prologue
#define S_G  196608   // 8192: g[128][16] f32
#define S_XN 204800   // 512:  xn[128]
#define SMEM_REQ 205312

__device__ __forceinline__ uint32_t smem_u32(const void* p) {
    uint32_t a;
    asm("{ .reg .u64 t; cvta.to.shared.u64 t, %1; cvt.u32.u64 %0, t; }" : "=r"(a) : "l"(p));
    return a;
}
__device__ __forceinline__ void ldsm4(uint32_t* r, uint32_t addr) {
    asm volatile("ldmatrix.sync.aligned.m8n8.x4.shared.b16 {%0,%1,%2,%3}, [%4];"
        : "=r"(r[0]), "=r"(r[1]), "=r"(r[2]), "=r"(r[3]) : "r"(addr));
}
__device__ __forceinline__ void mma_bf16(float* c, const uint32_t* a, const uint32_t* b) {
    asm volatile("mma.sync.aligned.m16n8k16.row.col.f32.bf16.bf16.f32 "
        "{%0,%1,%2,%3}, {%4,%5,%6,%7}, {%8,%9}, {%0,%1,%2,%3};"
        : "+f"(c[0]), "+f"(c[1]), "+f"(c[2]), "+f"(c[3])
        : "r"(a[0]), "r"(a[1]), "r"(a[2]), "r"(a[3]), "r"(b[0]), "r"(b[1]));
}
__device__ __forceinline__ void cpasync16(uint32_t dst, const void* src) {
    asm volatile("cp.async.cg.shared.global [%0], [%1], 16;" :: "r"(dst), "l"(src));
}
#define CP_COMMIT() asm volatile("cp.async.commit_group;" ::: "memory")
#define CP_WAIT0()  asm volatile("cp.async.wait_group 0;" ::: "memory")
#define CP_WAIT1()  asm volatile("cp.async.wait_group 1;" ::: "memory")

__device__ __forceinline__ uint32_t addrB(uint32_t base, int n0, int c0, int rb, int lane) {
    int row = n0 + ((lane >> 4) << 3) + (lane & 7);
    int c = c0 + ((lane >> 3) & 1);
    return base + row * rb + ((c ^ (row & 7)) << 4);
}
__device__ __forceinline__ uint32_t pack2(__nv_bfloat16 a, __nv_bfloat16 b) {
    return ((uint32_t)__bfloat16_as_ushort(b) << 16) | (uint32_t)__bfloat16_as_ushort(a);
}
__device__ __forceinline__ void split_bf(float v, __nv_bfloat16& h, __nv_bfloat16& l) {
    h = __float2bfloat16(v);
    l = __float2bfloat16(v - __bfloat162float(h));
}
__device__ __forceinline__ uint32_t packhi2(float a, float b) {
    return pack2(__float2bfloat16(a), __float2bfloat16(b));
}
__device__ __forceinline__ uint32_t packlo2(float a, float b) {
    __nv_bfloat16 ha = __float2bfloat16(a), hb = __float2bfloat16(b);
    return pack2(__float2bfloat16(a - __bfloat162float(ha)),
                 __float2bfloat16(b - __bfloat162float(hb)));
}
__device__ __forceinline__ float b2f_lo(uint32_t u) { return __uint_as_float(u << 16); }
__device__ __forceinline__ float b2f_hi(uint32_t u) { return __uint_as_float(u & 0xFFFF0000u); }

// ---------------- preprocess ----------------
__global__ void pp_kernel(const float* __restrict__ K, const float* __restrict__ V,
                          const float* __restrict__ wg) {
    const int total = EE * MM * DD;
    for (int idx = blockIdx.x * blockDim.x + threadIdx.x; idx < total;
         idx += gridDim.x * blockDim.x) {
        __nv_bfloat16 h, l;
        split_bf(K[idx], h, l);
        g_Khi[idx] = h; g_Klo[idx] = l;
        int e = idx >> 14, rem = idx & 16383, d = rem >> 6, m = rem & 63;
        split_bf(V[(e << 14) + m * DD + d], h, l);
        g_Vthi[idx] = h; g_Vtlo[idx] = l;
        if (idx < EE * DD) { split_bf(wg[idx], h, l); g_wghi[idx] = h; g_wglo[idx] = l; }
    }
}

// ================= fused kernel: 8 warps, K double-buffer, V rotate =================
__global__ __launch_bounds__(NT, 1) void more_mma(
    const float* __restrict__ x, const float* __restrict__ bg,
    float* __restrict__ out)
{
    extern __shared__ char smem[];
    const uint32_t sb = smem_u32(smem);

    const int tid  = threadIdx.x;
    const int warp = tid >> 5;              // 0..7
    const int lane = tid & 31;
    const int tig  = lane & 3;
    const int rb   = blockIdx.x * RT;
    const int rowA = 16 * warp + (lane >> 2);   // 0..127
    const int rowB = rowA + 8;

    float* g_s  = (float*)(smem + S_G);
    float* xn_s = (float*)(smem + S_XN);

    // ---- x -> persistent bf16 hi/lo A-fragment registers (fully unrolled) ----
    uint32_t xh[64], xl[64];
    {
        const float* xpA = &x[(size_t)(rb + rowA) * DD + 2 * tig];
        const float* xpB = &x[(size_t)(rb + rowB) * DD + 2 * tig];
        #pragma unroll
        for (int ks = 0; ks < 16; ks++) {
            float2 g0 = *(const float2*)&xpA[16 * ks];
            float2 g1 = *(const float2*)&xpB[16 * ks];
            float2 g2 = *(const float2*)&xpA[16 * ks + 8];
            float2 g3 = *(const float2*)&xpB[16 * ks + 8];
            xh[4*ks+0] = packhi2(g0.x, g0.y);  xl[4*ks+0] = packlo2(g0.x, g0.y);
            xh[4*ks+1] = packhi2(g1.x, g1.y);  xl[4*ks+1] = packlo2(g1.x, g1.y);
            xh[4*ks+2] = packhi2(g2.x, g2.y);  xl[4*ks+2] = packlo2(g2.x, g2.y);
            xh[4*ks+3] = packhi2(g3.x, g3.y);  xl[4*ks+3] = packlo2(g3.x, g3.y);
        }
    }
    // wg hi -> S_V, lo -> S_V+32768 (16 rows x 512B = 512 uint4 each)
    {
        const uint4* Wh = (const uint4*)g_wghi;
        const uint4* Wl = (const uint4*)g_wglo;
        #pragma unroll
        for (int i = 0; i < 2; i++) {
            int u = i * NT + tid;
            int row = u >> 5, c = u & 31;
            int o = row * 512 + ((c ^ (row & 7)) << 4);
            *(uint4*)(smem + S_V + o)         = Wh[u];
            *(uint4*)(smem + S_V + 32768 + o) = Wl[u];
        }
    }
    // x row norms -> smem
    if (tid < RT) {
        const float4* xr = (const float4*)&x[(size_t)(rb + tid) * DD];
        float s = 0.f;
        #pragma unroll 8
        for (int j = 0; j < 64; j++) {
            float4 v = xr[j];
            s = fmaf(v.x, v.x, fmaf(v.y, v.y, fmaf(v.z, v.z, fmaf(v.w, v.w, s))));
        }
        xn_s[tid] = sqrtf(s);
    }
    __syncthreads();

    // ---- gate GEMM: N=16 per warp, 3-term, A from registers ----
    {
        float accg[2][4] = {};
        uint32_t bh[4], bl[4];
        #pragma unroll
        for (int ks = 0; ks < 16; ks++) {
            ldsm4(bh, addrB(sb + S_V,         0, 2 * ks, 512, lane));
            ldsm4(bl, addrB(sb + S_V + 32768, 0, 2 * ks, 512, lane));
            const uint32_t* ah = xh + 4 * ks;
            const uint32_t* al = xl + 4 * ks;
            mma_bf16(accg[0], ah, bh); mma_bf16(accg[1], ah, bh + 2);
            mma_bf16(accg[0], al, bh); mma_bf16(accg[1], al, bh + 2);
            mma_bf16(accg[0], ah, bl); mma_bf16(accg[1], ah, bl + 2);
        }
        #pragma unroll
        for (int t = 0; t < 2; t++) {
            int c0 = 8 * t + 2 * tig;
            float gA0 = 1.f / (1.f + __expf(-(accg[t][0] + bg[c0])));
            float gA1 = 1.f / (1.f + __expf(-(accg[t][1] + bg[c0 + 1])));
            float gB0 = 1.f / (1.f + __expf(-(accg[t][2] + bg[c0])));
            float gB1 = 1.f / (1.f + __expf(-(accg[t][3] + bg[c0 + 1])));
            *(float2*)&out[O_G + (size_t)(rb + rowA) * EE + c0] = make_float2(gA0, gA1);
            *(float2*)&out[O_G + (size_t)(rb + rowB) * EE + c0] = make_float2(gB0, gB1);
            *(float2*)&g_s[rowA * EE + c0] = make_float2(gA0, gA1);
            *(float2*)&g_s[rowB * EE + c0] = make_float2(gB0, gB1);
        }
    }
    __syncthreads();   // wg reads + g_s stores done -> S_V reusable

    // prologue prefetch: K[0] -> KA (group), V[0] -> S_V (group)
    {
        const uint4* Kh = (const uint4*)g_Khi;
        const uint4* Kl = (const uint4*)g_Klo;
        #pragma unroll
        for (int i = 0; i < 8; i++) {
            int u = i * NT + tid;
            int kr = u >> 5, kc = u & 31;
            uint32_t o = (uint32_t)(kr * 512 + ((kc ^ (kr & 7)) << 4));
            cpasync16(sb + S_KA + o,         Kh + u);
            cpasync16(sb + S_KA + 32768 + o, Kl + u);
        }
        CP_COMMIT();
        const uint4* Vh = (const uint4*)g_Vthi;
        const uint4* Vl = (const uint4*)g_Vtlo;
        #pragma unroll
        for (int i = 0; i < 8; i++) {
            int u = i * NT + tid;
            int vr = u >> 3, vc = u & 7;
            uint32_t o = (uint32_t)(vr * 128 + ((vc ^ (vr & 7)) << 4));
            cpasync16(sb + S_V + o,         Vh + u);
            cpasync16(sb + S_V + 32768 + o, Vl + u);
        }
        CP_COMMIT();
    }

    float bestfA = -INFINITY, bestfB = -INFINITY;
    int   besteA = 0, besteB = 0;

    for (int e = 0; e < EE; e++) {
        // S1: K(e) ready (V(e)/older also complete except newest group)
        if (e == 0) { CP_WAIT0(); } else { CP_WAIT1(); }
        __syncthreads();

        const uint32_t kb = sb + ((e & 1) ? S_KB : S_KA);

        // issue K(e+1) into the other buffer (hides under the whole expert)
        if (e + 1 < EE) {
            const uint4* Kh = (const uint4*)g_Khi + (e + 1) * 2048;
            const uint4* Kl = (const uint4*)g_Klo + (e + 1) * 2048;
            const uint32_t ko = sb + (((e + 1) & 1) ? S_KB : S_KA);
            #pragma unroll
            for (int i = 0; i < 8; i++) {
                int u = i * NT + tid;
                int kr = u >> 5, kc = u & 31;
                uint32_t o = (uint32_t)(kr * 512 + ((kc ^ (kr & 7)) << 4));
                cpasync16(ko + o,         Kh + u);
                cpasync16(ko + 32768 + o, Kl + u);
            }
            CP_COMMIT();
        }

        // ======== GEMM1: logits[16 rows x 64 cols per warp], 3-term ========
        float acc[8][4] = {};
        {
            uint32_t bh[4], bl[4];
            #pragma unroll
            for (int ks = 0; ks < 16; ks++) {
                const uint32_t* ah = xh + 4 * ks;
                const uint32_t* al = xl + 4 * ks;
                #pragma unroll
                for (int p = 0; p < 4; p++) {
                    ldsm4(bh, addrB(kb,         16 * p, 2 * ks, 512, lane));
                    ldsm4(bl, addrB(kb + 32768, 16 * p, 2 * ks, 512, lane));
                    mma_bf16(acc[2*p],   ah, bh); mma_bf16(acc[2*p+1], ah, bh + 2);
                    mma_bf16(acc[2*p],   al, bh); mma_bf16(acc[2*p+1], al, bh + 2);
                    mma_bf16(acc[2*p],   ah, bl); mma_bf16(acc[2*p+1], ah, bl + 2);
                }
            }
        }

        // ======== softmax (full row in-warp; logits ~N(0,1/256): no max-sub) ========
        uint32_t aH[16], aL[16];
        {
            float sA = 0.f, sB = 0.f;
            #pragma unroll
            for (int t = 0; t < 8; t++) {
                acc[t][0] = __expf(acc[t][0] * 0.0625f); sA += acc[t][0];
                acc[t][1] = __expf(acc[t][1] * 0.0625f); sA += acc[t][1];
                acc[t][2] = __expf(acc[t][2] * 0.0625f); sB += acc[t][2];
                acc[t][3] = __expf(acc[t][3] * 0.0625f); sB += acc[t][3];
            }
            sA += __shfl_xor_sync(0xffffffffu, sA, 1);
            sA += __shfl_xor_sync(0xffffffffu, sA, 2);
            sB += __shfl_xor_sync(0xffffffffu, sB, 1);
            sB += __shfl_xor_sync(0xffffffffu, sB, 2);
            float iA = 1.f / sA, iB = 1.f / sB;
            float* oaA = &out[O_A + ((size_t)(rb + rowA) * EE + e) * MM];
            float* oaB = &out[O_A + ((size_t)(rb + rowB) * EE + e) * MM];
            #pragma unroll
            for (int t = 0; t < 8; t++) {
                float a0 = acc[t][0] * iA, a1 = acc[t][1] * iA;
                float b0 = acc[t][2] * iB, b1 = acc[t][3] * iB;
                *(float2*)&oaA[8*t + 2*tig] = make_float2(a0, a1);
                *(float2*)&oaB[8*t + 2*tig] = make_float2(b0, b1);
                acc[t][0] = a0; acc[t][1] = a1; acc[t][2] = b0; acc[t][3] = b1;
            }
            // C-frag -> A-frag in registers
            #pragma unroll
            for (int ks = 0; ks < 4; ks++) {
                aH[4*ks+0] = packhi2(acc[2*ks][0],   acc[2*ks][1]);
                aH[4*ks+1] = packhi2(acc[2*ks][2],   acc[2*ks][3]);
                aH[4*ks+2] = packhi2(acc[2*ks+1][0], acc[2*ks+1][1]);
                aH[4*ks+3] = packhi2(acc[2*ks+1][2], acc[2*ks+1][3]);
                aL[4*ks+0] = packlo2(acc[2*ks][0],   acc[2*ks][1]);
                aL[4*ks+1] = packlo2(acc[2*ks][2],   acc[2*ks][3]);
                aL[4*ks+2] = packlo2(acc[2*ks+1][0], acc[2*ks+1][1]);
                aL[4*ks+3] = packlo2(acc[2*ks+1][2], acc[2*ks+1][3]);
            }
        }

        // S2: V(e) ready (only the K(e+1) group may remain in flight)
        if (e + 1 < EE) { CP_WAIT1(); } else { CP_WAIT0(); }
        __syncthreads();

        // ======== GEMM2: y[16 rows x 256 cols], 3-term; x from registers ========
        float pxA = 0.f, pnA = 0.f, pxB = 0.f, pnB = 0.f;
        float* oyA = &out[O_Y + ((size_t)(rb + rowA) * EE + e) * DD];
        float* oyB = &out[O_Y + ((size_t)(rb + rowB) * EE + e) * DD];
        #pragma unroll
        for (int ch = 0; ch < 16; ch++) {
            float acc2[2][4] = {};
            {
                uint32_t bh[4], bl[4];
                #pragma unroll
                for (int ks = 0; ks < 4; ks++) {
                    ldsm4(bh, addrB(sb + S_V,         16 * ch, 2 * ks, 128, lane));
                    ldsm4(bl, addrB(sb + S_V + 32768, 16 * ch, 2 * ks, 128, lane));
                    const uint32_t* ah = aH + 4 * ks;
                    const uint32_t* al = aL + 4 * ks;
                    mma_bf16(acc2[0], ah, bh); mma_bf16(acc2[1], ah, bh + 2);
                    mma_bf16(acc2[0], al, bh); mma_bf16(acc2[1], al, bh + 2);
                    mma_bf16(acc2[0], ah, bl); mma_bf16(acc2[1], ah, bl + 2);
                }
            }
            #pragma unroll
            for (int j = 0; j < 2; j++) {
                int d = 16 * ch + 8 * j + 2 * tig;
                float y0 = acc2[j][0], y1 = acc2[j][1];
                float z0 = acc2[j][2], z1 = acc2[j][3];
                *(float2*)&oyA[d] = make_float2(y0, y1);
                *(float2*)&oyB[d] = make_float2(z0, z1);
                uint32_t uhA = xh[4*ch + 2*j + 0], ulA = xl[4*ch + 2*j + 0];
                uint32_t uhB = xh[4*ch + 2*j + 1], ulB = xl[4*ch + 2*j + 1];
                float xA0 = b2f_lo(uhA) + b2f_lo(ulA), xA1 = b2f_hi(uhA) + b2f_hi(ulA);
                float xB0 = b2f_lo(uhB) + b2f_lo(ulB), xB1 = b2f_hi(uhB) + b2f_hi(ulB);
                pxA = fmaf(xA0, y0, fmaf(xA1, y1, pxA));
                pnA = fmaf(y0, y0, fmaf(y1, y1, pnA));
                pxB = fmaf(xB0, z0, fmaf(xB1, z1, pxB));
                pnB = fmaf(z0, z0, fmaf(z1, z1, pnB));
            }
        }
        // S3: all V(e) reads done
        __syncthreads();

        // issue V(e+1) (hides under px/pn tail + S1 + GEMM1(e+1) + softmax)
        if (e + 1 < EE) {
            const uint4* Vh = (const uint4*)g_Vthi + (e + 1) * 2048;
            const uint4* Vl = (const uint4*)g_Vtlo + (e + 1) * 2048;
            #pragma unroll
            for (int i = 0; i < 8; i++) {
                int u = i * NT + tid;
                int vr = u >> 3, vc = u & 7;
                uint32_t o = (uint32_t)(vr * 128 + ((vc ^ (vr & 7)) << 4));
                cpasync16(sb + S_V + o,         Vh + u);
                cpasync16(sb + S_V + 32768 + o, Vl + u);
            }
            CP_COMMIT();
        }

        // px/pn quad-reduce + in-register argmax
        pxA += __shfl_xor_sync(0xffffffffu, pxA, 1);
        pxA += __shfl_xor_sync(0xffffffffu, pxA, 2);
        pnA += __shfl_xor_sync(0xffffffffu, pnA, 1);
        pnA += __shfl_xor_sync(0xffffffffu, pnA, 2);
        pxB += __shfl_xor_sync(0xffffffffu, pxB, 1);
        pxB += __shfl_xor_sync(0xffffffffu, pxB, 2);
        pnB += __shfl_xor_sync(0xffffffffu, pnB, 1);
        pnB += __shfl_xor_sync(0xffffffffu, pnB, 2);
        if (tig == 0) {
            float cosA = pxA / (xn_s[rowA] * sqrtf(pnA) + 1e-8f);
            float cosB = pxB / (xn_s[rowB] * sqrtf(pnB) + 1e-8f);
            float fA = g_s[rowA * EE + e] * cosA;
            float fB = g_s[rowB * EE + e] * cosB;
            if (fA > bestfA) { bestfA = fA; besteA = e; }
            if (fB > bestfB) { bestfB = fB; besteB = e; }
        }
    }

    if (tig == 0) {
        out[O_W + rb + rowA] = (float)besteA;
        out[O_W + rb + rowB] = (float)besteB;
        out[O_S + rb + rowA] = bestfA;
        out[O_S + rb + rowB] = bestfB;
    }
}

extern "C" void kernel_launch(void* const* d_in, const int* in_sizes, int n_in,
                              void* d_out, int out_size) {
    (void)in_sizes; (void)n_in; (void)out_size;
    const float* x  = (const float*)d_in[0];
    const float* K  = (const float*)d_in[1];
    const float* V  = (const float*)d_in[2];
    const float* wg = (const float*)d_in[3];
    const float* bg = (const float*)d_in[4];
    float* out = (float*)d_out;

    pp_kernel<<<256, 256>>>(K, V, wg);

    cudaFuncSetAttribute(more_mma, cudaFuncAttributeMaxDynamicSharedMemorySize, SMEM_REQ);
    more_mma<<<BB / RT, NT, SMEM_REQ>>>(x, bg, out);
}

// round 14
// speedup vs baseline: 1.0677x; 1.0677x over previous
#include <cuda_runtime.h>
#include <cuda_bf16.h>
#include <cstdint>
#include <math.h>

#define BB 32768
#define EE 16
#define MM 64
#define DD 256
#define RT 64
#define NT 128

#define O_W ((size_t)0)
#define O_S ((size_t)BB)
#define O_Y ((size_t)(2*BB))
#define O_G (O_Y + (size_t)BB*EE*DD)
#define O_A (O_G + (size_t)BB*EE)

// preconverted bf16 hi/lo operands
__device__ __nv_bfloat16 g_Khi[EE*MM*DD];
__device__ __nv_bfloat16 g_Klo[EE*MM*DD];
__device__ __nv_bfloat16 g_Vthi[EE*DD*MM];   // [E][D][M]
__device__ __nv_bfloat16 g_Vtlo[EE*DD*MM];
__device__ __nv_bfloat16 g_wghi[EE*DD];
__device__ __nv_bfloat16 g_wglo[EE*DD];

// smem: 3-buffer ring of 32KB quanta + g/xn staging
#define S_B0 0
#define S_B1 32768
#define S_B2 65536
#define S_G  98304    // 64*16*4 = 4096
#define S_XN 102400   // 256
#define SMEM_REQ 102656

__device__ __forceinline__ uint32_t smem_u32(const void* p) {
    uint32_t a;
    asm("{ .reg .u64 t; cvta.to.shared.u64 t, %1; cvt.u32.u64 %0, t; }" : "=r"(a) : "l"(p));
    return a;
}
__device__ __forceinline__ void ldsm4(uint32_t* r, uint32_t addr) {
    asm volatile("ldmatrix.sync.aligned.m8n8.x4.shared.b16 {%0,%1,%2,%3}, [%4];"
        : "=r"(r[0]), "=r"(r[1]), "=r"(r[2]), "=r"(r[3]) : "r"(addr));
}
__device__ __forceinline__ void mma_bf16(float* c, const uint32_t* a, const uint32_t* b) {
    asm volatile("mma.sync.aligned.m16n8k16.row.col.f32.bf16.bf16.f32 "
        "{%0,%1,%2,%3}, {%4,%5,%6,%7}, {%8,%9}, {%0,%1,%2,%3};"
        : "+f"(c[0]), "+f"(c[1]), "+f"(c[2]), "+f"(c[3])
        : "r"(a[0]), "r"(a[1]), "r"(a[2]), "r"(a[3]), "r"(b[0]), "r"(b[1]));
}
__device__ __forceinline__ void cpasync16(uint32_t dst, const void* src) {
    asm volatile("cp.async.cg.shared.global [%0], [%1], 16;" :: "r"(dst), "l"(src));
}
#define CP_COMMIT() asm volatile("cp.async.commit_group;" ::: "memory")
#define CP_WAIT0()  asm volatile("cp.async.wait_group 0;" ::: "memory")
#define CP_WAIT1()  asm volatile("cp.async.wait_group 1;" ::: "memory")

__device__ __forceinline__ uint32_t addrB(uint32_t base, int n0, int c0, int rb, int lane) {
    int row = n0 + ((lane >> 4) << 3) + (lane & 7);
    int c = c0 + ((lane >> 3) & 1);
    return base + row * rb + ((c ^ (row & 7)) << 4);
}
__device__ __forceinline__ uint32_t pack2(__nv_bfloat16 a, __nv_bfloat16 b) {
    return ((uint32_t)__bfloat16_as_ushort(b) << 16) | (uint32_t)__bfloat16_as_ushort(a);
}
__device__ __forceinline__ void split_bf(float v, __nv_bfloat16& h, __nv_bfloat16& l) {
    h = __float2bfloat16(v);
    l = __float2bfloat16(v - __bfloat162float(h));
}
__device__ __forceinline__ uint32_t packhi2(float a, float b) {
    return pack2(__float2bfloat16(a), __float2bfloat16(b));
}
__device__ __forceinline__ uint32_t packlo2(float a, float b) {
    __nv_bfloat16 ha = __float2bfloat16(a), hb = __float2bfloat16(b);
    return pack2(__float2bfloat16(a - __bfloat162float(ha)),
                 __float2bfloat16(b - __bfloat162float(hb)));
}
__device__ __forceinline__ float b2f_lo(uint32_t u) { return __uint_as_float(u << 16); }
__device__ __forceinline__ float b2f_hi(uint32_t u) { return __uint_as_float(u & 0xFFFF0000u); }

// ---------------- preprocess ----------------
__global__ void pp_kernel(const float* __restrict__ K, const float* __restrict__ V,
                          const float* __restrict__ wg) {
    const int total = EE * MM * DD;
    for (int idx = blockIdx.x * blockDim.x + threadIdx.x; idx < total;
         idx += gridDim.x * blockDim.x) {
        __nv_bfloat16 h, l;
        split_bf(K[idx], h, l);
        g_Khi[idx] = h; g_Klo[idx] = l;
        int e = idx >> 14, rem = idx & 16383, d = rem >> 6, m = rem & 63;
        split_bf(V[(e << 14) + m * DD + d], h, l);
        g_Vthi[idx] = h; g_Vtlo[idx] = l;
        if (idx < EE * DD) { split_bf(wg[idx], h, l); g_wghi[idx] = h; g_wglo[idx] = l; }
    }
}

// issue one 32KB quantum q (q = 4e + sub; sub 0/1 = K d-half, 2/3 = V d-half)
__device__ __forceinline__ void issue_q(uint32_t sb, int q, int tid) {
    if (q >= 4 * EE) return;
    const int e = q >> 2, sub = q & 3;
    const uint32_t buf = sb + (uint32_t)(q % 3) * 32768u;
    if (sub < 2) {
        const uint4* Kh = (const uint4*)g_Khi + e * 2048 + sub * 16;
        const uint4* Kl = (const uint4*)g_Klo + e * 2048 + sub * 16;
        #pragma unroll
        for (int i = 0; i < 8; i++) {
            int u = i * NT + tid;               // 0..1023
            int m = u >> 4, c = u & 15;
            uint32_t dst = buf + (uint32_t)(m * 256 + ((c ^ (m & 7)) << 4));
            const uint4* sh = Kh + m * 32 + c;
            const uint4* sl = Kl + m * 32 + c;
            cpasync16(dst,          sh);
            cpasync16(dst + 16384u, sl);
        }
    } else {
        const int h = sub - 2;
        const uint4* Vh = (const uint4*)g_Vthi + e * 2048 + h * 1024;
        const uint4* Vl = (const uint4*)g_Vtlo + e * 2048 + h * 1024;
        #pragma unroll
        for (int i = 0; i < 8; i++) {
            int u = i * NT + tid;               // 0..1023
            int dd = u >> 3, c = u & 7;
            uint32_t dst = buf + (uint32_t)(dd * 128 + ((c ^ (dd & 7)) << 4));
            cpasync16(dst,          Vh + u);
            cpasync16(dst + 16384u, Vl + u);
        }
    }
    CP_COMMIT();
}

// GEMM1 half: 8 global-ks steps starting at KS0, K-half tile at kb (rb=256)
template<int KS0>
__device__ __forceinline__ void gemm1_half(float (&acc)[8][4],
                                           const uint32_t (&xh)[64], const uint32_t (&xl)[64],
                                           uint32_t kb, int lane) {
    uint32_t bh[4], bl[4];
    #pragma unroll
    for (int ksl = 0; ksl < 8; ksl++) {
        const uint32_t* ah = &xh[4 * (KS0 + ksl)];
        const uint32_t* al = &xl[4 * (KS0 + ksl)];
        #pragma unroll
        for (int p = 0; p < 4; p++) {
            ldsm4(bh, addrB(kb,          16 * p, 2 * ksl, 256, lane));
            ldsm4(bl, addrB(kb + 16384u, 16 * p, 2 * ksl, 256, lane));
            mma_bf16(acc[2*p],   ah, bh); mma_bf16(acc[2*p+1], ah, bh + 2);
            mma_bf16(acc[2*p],   al, bh); mma_bf16(acc[2*p+1], al, bh + 2);
            mma_bf16(acc[2*p],   ah, bl); mma_bf16(acc[2*p+1], ah, bl + 2);
        }
    }
}

// ================= main fused kernel: 2 CTAs/SM, quantum pipeline =================
__global__ __launch_bounds__(NT, 2) void more_mma(
    const float* __restrict__ x, const float* __restrict__ bg,
    float* __restrict__ out)
{
    extern __shared__ char smem[];
    const uint32_t sb = smem_u32(smem);

    const int tid  = threadIdx.x;
    const int warp = tid >> 5;              // 0..3
    const int lane = tid & 31;
    const int tig  = lane & 3;
    const int rb   = blockIdx.x * RT;
    const int rowA = 16 * warp + (lane >> 2);   // 0..63
    const int rowB = rowA + 8;

    float* g_s  = (float*)(smem + S_G);
    float* xn_s = (float*)(smem + S_XN);

    // ---- x -> persistent bf16 hi/lo A-fragment registers (fully unrolled) ----
    uint32_t xh[64], xl[64];
    {
        const float* xpA = &x[(size_t)(rb + rowA) * DD + 2 * tig];
        const float* xpB = &x[(size_t)(rb + rowB) * DD + 2 * tig];
        #pragma unroll
        for (int ks = 0; ks < 16; ks++) {
            float2 g0 = *(const float2*)&xpA[16 * ks];
            float2 g1 = *(const float2*)&xpB[16 * ks];
            float2 g2 = *(const float2*)&xpA[16 * ks + 8];
            float2 g3 = *(const float2*)&xpB[16 * ks + 8];
            xh[4*ks+0] = packhi2(g0.x, g0.y);  xl[4*ks+0] = packlo2(g0.x, g0.y);
            xh[4*ks+1] = packhi2(g1.x, g1.y);  xl[4*ks+1] = packlo2(g1.x, g1.y);
            xh[4*ks+2] = packhi2(g2.x, g2.y);  xl[4*ks+2] = packlo2(g2.x, g2.y);
            xh[4*ks+3] = packhi2(g3.x, g3.y);  xl[4*ks+3] = packlo2(g3.x, g3.y);
        }
    }
    // wg -> buffer0: hi @+0, lo @+8192 (16 rows x 512B)
    {
        const uint4* Wh = (const uint4*)g_wghi;
        const uint4* Wl = (const uint4*)g_wglo;
        #pragma unroll
        for (int i = 0; i < 4; i++) {
            int u = i * NT + tid;               // 0..511
            int row = u >> 5, c = u & 31;
            int o = row * 512 + ((c ^ (row & 7)) << 4);
            *(uint4*)(smem + S_B0 + o)        = Wh[u];
            *(uint4*)(smem + S_B0 + 8192 + o) = Wl[u];
        }
    }
    // x row norms -> smem
    if (tid < RT) {
        const float4* xr = (const float4*)&x[(size_t)(rb + tid) * DD];
        float s = 0.f;
        #pragma unroll 8
        for (int j = 0; j < 64; j++) {
            float4 v = xr[j];
            s = fmaf(v.x, v.x, fmaf(v.y, v.y, fmaf(v.z, v.z, fmaf(v.w, v.w, s))));
        }
        xn_s[tid] = sqrtf(s);
    }
    __syncthreads();

    // ---- gate GEMM: N=16, 3-term, A from registers ----
    {
        float accg[2][4] = {};
        uint32_t bh[4], bl[4];
        #pragma unroll
        for (int ks = 0; ks < 16; ks++) {
            ldsm4(bh, addrB(sb + S_B0,        0, 2 * ks, 512, lane));
            ldsm4(bl, addrB(sb + S_B0 + 8192, 0, 2 * ks, 512, lane));
            const uint32_t* ah = &xh[4 * ks];
            const uint32_t* al = &xl[4 * ks];
            mma_bf16(accg[0], ah, bh); mma_bf16(accg[1], ah, bh + 2);
            mma_bf16(accg[0], al, bh); mma_bf16(accg[1], al, bh + 2);
            mma_bf16(accg[0], ah, bl); mma_bf16(accg[1], ah, bl + 2);
        }
        #pragma unroll
        for (int t = 0; t < 2; t++) {
            int c0 = 8 * t + 2 * tig;
            float gA0 = 1.f / (1.f + __expf(-(accg[t][0] + bg[c0])));
            float gA1 = 1.f / (1.f + __expf(-(accg[t][1] + bg[c0 + 1])));
            float gB0 = 1.f / (1.f + __expf(-(accg[t][2] + bg[c0])));
            float gB1 = 1.f / (1.f + __expf(-(accg[t][3] + bg[c0 + 1])));
            *(float2*)&out[O_G + (size_t)(rb + rowA) * EE + c0] = make_float2(gA0, gA1);
            *(float2*)&out[O_G + (size_t)(rb + rowB) * EE + c0] = make_float2(gB0, gB1);
            *(float2*)&g_s[rowA * EE + c0] = make_float2(gA0, gA1);
            *(float2*)&g_s[rowB * EE + c0] = make_float2(gB0, gB1);
        }
    }
    __syncthreads();   // wg reads + g_s stores done -> buffer0 free

    // prologue: issue q0, q1 (two groups)
    issue_q(sb, 0, tid);
    issue_q(sb, 1, tid);

    float bestfA = -INFINITY, bestfB = -INFINITY;
    int   besteA = 0, besteB = 0;

    for (int e = 0; e < EE; e++) {
        const int q0 = 4 * e;
        float acc[8][4];
        #pragma unroll
        for (int t = 0; t < 8; t++) { acc[t][0]=0.f; acc[t][1]=0.f; acc[t][2]=0.f; acc[t][3]=0.f; }

        // ---- phase A: GEMM1 d 0..127 ----
        CP_WAIT1();
        __syncthreads();
        issue_q(sb, q0 + 2, tid);
        gemm1_half<0>(acc, xh, xl, sb + (uint32_t)(q0 % 3) * 32768u, lane);

        // ---- phase B: GEMM1 d 128..255 + softmax + attn ----
        CP_WAIT1();
        __syncthreads();
        issue_q(sb, q0 + 3, tid);
        gemm1_half<8>(acc, xh, xl, sb + (uint32_t)((q0 + 1) % 3) * 32768u, lane);

        uint32_t aH[16], aL[16];
        {
            float sA = 0.f, sB = 0.f;
            #pragma unroll
            for (int t = 0; t < 8; t++) {
                acc[t][0] = __expf(acc[t][0] * 0.0625f); sA += acc[t][0];
                acc[t][1] = __expf(acc[t][1] * 0.0625f); sA += acc[t][1];
                acc[t][2] = __expf(acc[t][2] * 0.0625f); sB += acc[t][2];
                acc[t][3] = __expf(acc[t][3] * 0.0625f); sB += acc[t][3];
            }
            sA += __shfl_xor_sync(0xffffffffu, sA, 1);
            sA += __shfl_xor_sync(0xffffffffu, sA, 2);
            sB += __shfl_xor_sync(0xffffffffu, sB, 1);
            sB += __shfl_xor_sync(0xffffffffu, sB, 2);
            float iA = 1.f / sA, iB = 1.f / sB;
            float* oaA = &out[O_A + ((size_t)(rb + rowA) * EE + e) * MM];
            float* oaB = &out[O_A + ((size_t)(rb + rowB) * EE + e) * MM];
            #pragma unroll
            for (int t = 0; t < 8; t++) {
                float a0 = acc[t][0] * iA, a1 = acc[t][1] * iA;
                float b0 = acc[t][2] * iB, b1 = acc[t][3] * iB;
                *(float2*)&oaA[8*t + 2*tig] = make_float2(a0, a1);
                *(float2*)&oaB[8*t + 2*tig] = make_float2(b0, b1);
                acc[t][0] = a0; acc[t][1] = a1; acc[t][2] = b0; acc[t][3] = b1;
            }
            #pragma unroll
            for (int ks = 0; ks < 4; ks++) {
                aH[4*ks+0] = packhi2(acc[2*ks][0],   acc[2*ks][1]);
                aH[4*ks+1] = packhi2(acc[2*ks][2],   acc[2*ks][3]);
                aH[4*ks+2] = packhi2(acc[2*ks+1][0], acc[2*ks+1][1]);
                aH[4*ks+3] = packhi2(acc[2*ks+1][2], acc[2*ks+1][3]);
                aL[4*ks+0] = packlo2(acc[2*ks][0],   acc[2*ks][1]);
                aL[4*ks+1] = packlo2(acc[2*ks][2],   acc[2*ks][3]);
                aL[4*ks+2] = packlo2(acc[2*ks+1][0], acc[2*ks+1][1]);
                aL[4*ks+3] = packlo2(acc[2*ks+1][2], acc[2*ks+1][3]);
            }
        }

        float pxA = 0.f, pnA = 0.f, pxB = 0.f, pnB = 0.f;
        float* oyA = &out[O_Y + ((size_t)(rb + rowA) * EE + e) * DD];
        float* oyB = &out[O_Y + ((size_t)(rb + rowB) * EE + e) * DD];

        // ---- phase C: GEMM2 d 0..127 ----
        CP_WAIT1();
        __syncthreads();
        issue_q(sb, q0 + 4, tid);
        {
            const uint32_t vb = sb + (uint32_t)((q0 + 2) % 3) * 32768u;
            #pragma unroll
            for (int chl = 0; chl < 8; chl++) {
                float acc2[2][4] = {};
                uint32_t bh[4], bl[4];
                #pragma unroll
                for (int ks = 0; ks < 4; ks++) {
                    ldsm4(bh, addrB(vb,          16 * chl, 2 * ks, 128, lane));
                    ldsm4(bl, addrB(vb + 16384u, 16 * chl, 2 * ks, 128, lane));
                    const uint32_t* ah = &aH[4 * ks];
                    const uint32_t* al = &aL[4 * ks];
                    mma_bf16(acc2[0], ah, bh); mma_bf16(acc2[1], ah, bh + 2);
                    mma_bf16(acc2[0], al, bh); mma_bf16(acc2[1], al, bh + 2);
                    mma_bf16(acc2[0], ah, bl); mma_bf16(acc2[1], ah, bl + 2);
                }
                #pragma unroll
                for (int j = 0; j < 2; j++) {
                    int d = 16 * chl + 8 * j + 2 * tig;
                    float y0 = acc2[j][0], y1 = acc2[j][1];
                    float z0 = acc2[j][2], z1 = acc2[j][3];
                    *(float2*)&oyA[d] = make_float2(y0, y1);
                    *(float2*)&oyB[d] = make_float2(z0, z1);
                    uint32_t uhA = xh[4*chl + 2*j + 0], ulA = xl[4*chl + 2*j + 0];
                    uint32_t uhB = xh[4*chl + 2*j + 1], ulB = xl[4*chl + 2*j + 1];
                    float xA0 = b2f_lo(uhA) + b2f_lo(ulA), xA1 = b2f_hi(uhA) + b2f_hi(ulA);
                    float xB0 = b2f_lo(uhB) + b2f_lo(ulB), xB1 = b2f_hi(uhB) + b2f_hi(ulB);
                    pxA = fmaf(xA0, y0, fmaf(xA1, y1, pxA));
                    pnA = fmaf(y0, y0, fmaf(y1, y1, pnA));
                    pxB = fmaf(xB0, z0, fmaf(xB1, z1, pxB));
                    pnB = fmaf(z0, z0, fmaf(z1, z1, pnB));
                }
            }
        }

        // ---- phase D: GEMM2 d 128..255 + familiarity ----
        if (e == EE - 1) { CP_WAIT0(); } else { CP_WAIT1(); }
        __syncthreads();
        issue_q(sb, q0 + 5, tid);
        {
            const uint32_t vb = sb + (uint32_t)((q0 + 3) % 3) * 32768u;
            #pragma unroll
            for (int chl = 0; chl < 8; chl++) {
                float acc2[2][4] = {};
                uint32_t bh[4], bl[4];
                #pragma unroll
                for (int ks = 0; ks < 4; ks++) {
                    ldsm4(bh, addrB(vb,          16 * chl, 2 * ks, 128, lane));
                    ldsm4(bl, addrB(vb + 16384u, 16 * chl, 2 * ks, 128, lane));
                    const uint32_t* ah = &aH[4 * ks];
                    const uint32_t* al = &aL[4 * ks];
                    mma_bf16(acc2[0], ah, bh); mma_bf16(acc2[1], ah, bh + 2);
                    mma_bf16(acc2[0], al, bh); mma_bf16(acc2[1], al, bh + 2);
                    mma_bf16(acc2[0], ah, bl); mma_bf16(acc2[1], ah, bl + 2);
                }
                #pragma unroll
                for (int j = 0; j < 2; j++) {
                    int d = 128 + 16 * chl + 8 * j + 2 * tig;
                    float y0 = acc2[j][0], y1 = acc2[j][1];
                    float z0 = acc2[j][2], z1 = acc2[j][3];
                    *(float2*)&oyA[d] = make_float2(y0, y1);
                    *(float2*)&oyB[d] = make_float2(z0, z1);
                    uint32_t uhA = xh[4*(8+chl) + 2*j + 0], ulA = xl[4*(8+chl) + 2*j + 0];
                    uint32_t uhB = xh[4*(8+chl) + 2*j + 1], ulB = xl[4*(8+chl) + 2*j + 1];
                    float xA0 = b2f_lo(uhA) + b2f_lo(ulA), xA1 = b2f_hi(uhA) + b2f_hi(ulA);
                    float xB0 = b2f_lo(uhB) + b2f_lo(ulB), xB1 = b2f_hi(uhB) + b2f_hi(ulB);
                    pxA = fmaf(xA0, y0, fmaf(xA1, y1, pxA));
                    pnA = fmaf(y0, y0, fmaf(y1, y1, pnA));
                    pxB = fmaf(xB0, z0, fmaf(xB1, z1, pxB));
                    pnB = fmaf(z0, z0, fmaf(z1, z1, pnB));
                }
            }
        }

        // px/pn quad-reduce + in-register argmax
        pxA += __shfl_xor_sync(0xffffffffu, pxA, 1);
        pxA += __shfl_xor_sync(0xffffffffu, pxA, 2);
        pnA += __shfl_xor_sync(0xffffffffu, pnA, 1);
        pnA += __shfl_xor_sync(0xffffffffu, pnA, 2);
        pxB += __shfl_xor_sync(0xffffffffu, pxB, 1);
        pxB += __shfl_xor_sync(0xffffffffu, pxB, 2);
        pnB += __shfl_xor_sync(0xffffffffu, pnB, 1);
        pnB += __shfl_xor_sync(0xffffffffu, pnB, 2);
        if (tig == 0) {
            float cosA = pxA / (xn_s[rowA] * sqrtf(pnA) + 1e-8f);
            float cosB = pxB / (xn_s[rowB] * sqrtf(pnB) + 1e-8f);
            float fA = g_s[rowA * EE + e] * cosA;
            float fB = g_s[rowB * EE + e] * cosB;
            if (fA > bestfA) { bestfA = fA; besteA = e; }
            if (fB > bestfB) { bestfB = fB; besteB = e; }
        }
    }

    if (tig == 0) {
        out[O_W + rb + rowA] = (float)besteA;
        out[O_W + rb + rowB] = (float)besteB;
        out[O_S + rb + rowA] = bestfA;
        out[O_S + rb + rowB] = bestfB;
    }
}

extern "C" void kernel_launch(void* const* d_in, const int* in_sizes, int n_in,
                              void* d_out, int out_size) {
    (void)in_sizes; (void)n_in; (void)out_size;
    const float* x  = (const float*)d_in[0];
    const float* K  = (const float*)d_in[1];
    const float* V  = (const float*)d_in[2];
    const float* wg = (const float*)d_in[3];
    const float* bg = (const float*)d_in[4];
    float* out = (float*)d_out;

    pp_kernel<<<256, 256>>>(K, V, wg);

    cudaFuncSetAttribute(more_mma, cudaFuncAttributeMaxDynamicSharedMemorySize, SMEM_REQ);
    more_mma<<<BB / RT, NT, SMEM_REQ>>>(x, bg, out);
}